// round 1
// baseline (speedup 1.0000x reference)
#include <cuda_runtime.h>
#include <math.h>

#define N_S 1024
#define XD  128
#define HID 256

// Scratch (no dynamic allocation allowed)
__device__ float g_xpT[HID * N_S];   // xp transposed: [h][j]
__device__ float g_ypb[N_S * HID];   // yp + b1:       [i][h]
__device__ float g_t0[N_S];
__device__ float g_lse[N_S];

// ---------------------------------------------------------------------------
// Projection: xp = x @ W1[:128], ypb = y @ W1[128:] + b1
// grid (128, 2), block 256. blockIdx.y==0 -> xp (transposed store), ==1 -> ypb
// ---------------------------------------------------------------------------
__global__ void proj_kernel(const float* __restrict__ x,
                            const float* __restrict__ y,
                            const float* __restrict__ W1,
                            const float* __restrict__ b1) {
    __shared__ float xs[8][XD];
    const int t  = threadIdx.x;          // 0..255 -> hidden index h
    const int rb = blockIdx.x * 8;       // row base (8 rows per block)
    const float* src = (blockIdx.y == 0) ? x : y;

    // stage 8 input rows (8*128 floats)
    for (int idx = t; idx < 8 * XD; idx += 256) {
        xs[idx / XD][idx % XD] = src[(rb + idx / XD) * XD + (idx % XD)];
    }
    __syncthreads();

    const float* Wb = W1 + (blockIdx.y == 0 ? 0 : XD * HID);
    float acc[8];
    #pragma unroll
    for (int r = 0; r < 8; r++) acc[r] = 0.f;

    #pragma unroll 4
    for (int k = 0; k < XD; k++) {
        const float w = Wb[k * HID + t];     // coalesced across threads
        #pragma unroll
        for (int r = 0; r < 8; r++) acc[r] = fmaf(xs[r][k], w, acc[r]);
    }

    if (blockIdx.y == 0) {
        #pragma unroll
        for (int r = 0; r < 8; r++) g_xpT[t * N_S + rb + r] = acc[r];
    } else {
        const float bb = b1[t];
        #pragma unroll
        for (int r = 0; r < 8; r++) g_ypb[(rb + r) * HID + t] = acc[r] + bb;
    }
}

// ---------------------------------------------------------------------------
// Main: T1[i,j] = sum_h relu(ypb[i,h] + xp[j,h]) * W2[h]  (+b2)
// grid 128 (8 i-rows per CTA, ALL 1024 j per CTA), block 256.
// Thread t owns j = 4t..4t+3 and all 8 local i's -> 32 accumulators.
// Epilogue: per-i block-wide exp-sum -> g_lse, diagonal -> g_t0.
// ---------------------------------------------------------------------------
__global__ void main_kernel(const float* __restrict__ W2,
                            const float* __restrict__ b2) {
    __shared__ float s_ypb[HID * 8];     // transposed: [h][i_local]
    __shared__ float s_w2[HID];
    __shared__ float red[256];

    const int t  = threadIdx.x;
    const int ib = blockIdx.x * 8;

    s_w2[t] = W2[t];                     // blockDim == HID == 256
    #pragma unroll
    for (int p = 0; p < 8; p++) {        // i_local = p, h = t
        s_ypb[t * 8 + p] = g_ypb[(ib + p) * HID + t];   // coalesced global read
    }
    __syncthreads();

    float acc[8][4];
    #pragma unroll
    for (int i = 0; i < 8; i++)
        #pragma unroll
        for (int c = 0; c < 4; c++) acc[i][c] = 0.f;

    #pragma unroll 2
    for (int h = 0; h < HID; h++) {
        const float4 xv = *reinterpret_cast<const float4*>(&g_xpT[h * N_S + t * 4]);
        const float  w  = s_w2[h];
        const float4 ya = *reinterpret_cast<const float4*>(&s_ypb[h * 8]);
        const float4 yb = *reinterpret_cast<const float4*>(&s_ypb[h * 8 + 4]);
        const float yv[8] = {ya.x, ya.y, ya.z, ya.w, yb.x, yb.y, yb.z, yb.w};
        const float xc[4] = {xv.x, xv.y, xv.z, xv.w};
        #pragma unroll
        for (int i = 0; i < 8; i++) {
            #pragma unroll
            for (int c = 0; c < 4; c++) {
                acc[i][c] = fmaf(fmaxf(yv[i] + xc[c], 0.f), w, acc[i][c]);
            }
        }
    }

    const float b2v = b2[0];

    // Per-i: exp-sum over this thread's 4 j's, capture diagonal, block-reduce.
    #pragma unroll
    for (int i = 0; i < 8; i++) {
        const int ig = ib + i;
        float s = 0.f;
        #pragma unroll
        for (int c = 0; c < 4; c++) {
            const float v = acc[i][c] + b2v;
            s += __expf(v);
            if (ig == 4 * t + c) g_t0[ig] = v;   // T0[i] = T1[i,i]
        }
        red[t] = s;
        __syncthreads();
        for (int off = 128; off > 0; off >>= 1) {
            if (t < off) red[t] += red[t + off];
            __syncthreads();
        }
        if (t == 0) g_lse[ig] = logf(red[0]);
        __syncthreads();
    }
}

// ---------------------------------------------------------------------------
// Finalize: lb = mean(T0) - (mean(lse) - log(N))
// ---------------------------------------------------------------------------
__global__ void finalize_kernel(float* __restrict__ out) {
    __shared__ float r1[256], r2[256];
    const int t = threadIdx.x;
    float a = 0.f, b = 0.f;
    #pragma unroll
    for (int p = 0; p < 4; p++) {
        a += g_t0[t + 256 * p];
        b += g_lse[t + 256 * p];
    }
    r1[t] = a; r2[t] = b;
    __syncthreads();
    for (int off = 128; off > 0; off >>= 1) {
        if (t < off) { r1[t] += r1[t + off]; r2[t] += r2[t + off]; }
        __syncthreads();
    }
    if (t == 0) {
        out[0] = r1[0] / (float)N_S - (r2[0] / (float)N_S - logf((float)N_S));
    }
}

// ---------------------------------------------------------------------------
extern "C" void kernel_launch(void* const* d_in, const int* in_sizes, int n_in,
                              void* d_out, int out_size) {
    const float* x  = (const float*)d_in[0];
    const float* y  = (const float*)d_in[1];
    const float* W1 = (const float*)d_in[2];
    const float* b1 = (const float*)d_in[3];
    const float* W2 = (const float*)d_in[4];
    const float* b2 = (const float*)d_in[5];

    proj_kernel<<<dim3(128, 2), 256>>>(x, y, W1, b1);
    main_kernel<<<128, 256>>>(W2, b2);
    finalize_kernel<<<1, 256>>>((float*)d_out);
}

// round 2
// speedup vs baseline: 1.3164x; 1.3164x over previous
#include <cuda_runtime.h>
#include <math.h>

#define N_S 1024
#define XD  128
#define HID 256

// Scratch (no dynamic allocation allowed)
__device__ __align__(16) float g_xpT[HID * N_S];   // xp transposed: [h][j]
__device__ __align__(16) float g_ypb[N_S * HID];   // yp + b1:       [i][h]
__device__ float g_t0[N_S];
__device__ float g_lse[N_S];

// ---------------------------------------------------------------------------
// packed f32x2 helpers (sm_103a)
// ---------------------------------------------------------------------------
__device__ __forceinline__ unsigned long long f2add(unsigned long long a,
                                                    unsigned long long b) {
    unsigned long long r;
    asm("add.rn.f32x2 %0,%1,%2;" : "=l"(r) : "l"(a), "l"(b));
    return r;
}
__device__ __forceinline__ unsigned long long f2fma(unsigned long long a,
                                                    unsigned long long b,
                                                    unsigned long long c) {
    unsigned long long r;
    asm("fma.rn.f32x2 %0,%1,%2,%3;" : "=l"(r) : "l"(a), "l"(b), "l"(c));
    return r;
}
__device__ __forceinline__ unsigned long long f2relu(unsigned long long a) {
    unsigned lo, hi;
    asm("mov.b64 {%0,%1},%2;" : "=r"(lo), "=r"(hi) : "l"(a));
    float flo = fmaxf(__uint_as_float(lo), 0.f);
    float fhi = fmaxf(__uint_as_float(hi), 0.f);
    unsigned long long r;
    asm("mov.b64 %0,{%1,%2};" : "=l"(r)
        : "r"(__float_as_uint(flo)), "r"(__float_as_uint(fhi)));
    return r;
}
__device__ __forceinline__ unsigned long long dupf(float v) {
    unsigned u = __float_as_uint(v);
    unsigned long long r;
    asm("mov.b64 %0,{%1,%1};" : "=l"(r) : "r"(u));
    return r;
}

// ---------------------------------------------------------------------------
// Projection: xp = x @ W1[:128] (stored transposed), ypb = y @ W1[128:] + b1
// grid (128, 2), block 256. Aggressive unroll to front-batch W LDGs (MLP).
// ---------------------------------------------------------------------------
__global__ void __launch_bounds__(256) proj_kernel(const float* __restrict__ x,
                                                   const float* __restrict__ y,
                                                   const float* __restrict__ W1,
                                                   const float* __restrict__ b1) {
    __shared__ float xs[8][XD];
    const int t  = threadIdx.x;          // hidden index h
    const int rb = blockIdx.x * 8;       // row base
    const float* src = (blockIdx.y == 0) ? x : y;

    for (int idx = t; idx < 8 * XD; idx += 256) {
        xs[idx / XD][idx % XD] = src[(rb + idx / XD) * XD + (idx % XD)];
    }
    __syncthreads();

    const float* Wb = W1 + (blockIdx.y == 0 ? 0 : XD * HID);
    float acc[8];
    #pragma unroll
    for (int r = 0; r < 8; r++) acc[r] = 0.f;

    #pragma unroll 32
    for (int k = 0; k < XD; k++) {
        const float w = Wb[k * HID + t];     // coalesced; batched by unroll
        #pragma unroll
        for (int r = 0; r < 8; r++) acc[r] = fmaf(xs[r][k], w, acc[r]);
    }

    if (blockIdx.y == 0) {
        #pragma unroll
        for (int r = 0; r < 8; r++) g_xpT[t * N_S + rb + r] = acc[r];
    } else {
        const float bb = b1[t];
        #pragma unroll
        for (int r = 0; r < 8; r++) g_ypb[(rb + r) * HID + t] = acc[r] + bb;
    }
}

// ---------------------------------------------------------------------------
// Main: T1[i,j] = sum_h relu(ypb[i,h] + xp[j,h]) * W2[h]  (+b2 in epilogue)
// grid 128 (8 i-rows per CTA, ALL 1024 j), block 512.
// Thread t owns the j-pair (2t, 2t+1) packed in one 64-bit reg, all 8 i's.
// Packed f32x2 add/fma; ypb & W2 pre-duplicated {v,v} in smem.
// ---------------------------------------------------------------------------
__global__ void __launch_bounds__(512) main_kernel(const float* __restrict__ W2,
                                                   const float* __restrict__ b2) {
    __shared__ __align__(16) unsigned long long s_y[HID][8];  // [h][i] dup pairs
    __shared__ __align__(16) unsigned long long s_w[HID];     // dup pairs
    __shared__ float red[16];

    const int t  = threadIdx.x;
    const int ib = blockIdx.x * 8;

    // stage ypb (dup-pair) and W2 (dup-pair)
    for (int idx = t; idx < HID * 8; idx += 512) {
        const int i = idx >> 8;          // 0..7
        const int h = idx & 255;         // coalesced over h
        s_y[h][i] = dupf(g_ypb[(ib + i) * HID + h]);
    }
    if (t < HID) s_w[t] = dupf(W2[t]);
    __syncthreads();

    unsigned long long acc[8];
    #pragma unroll
    for (int i = 0; i < 8; i++) acc[i] = 0ull;

    const unsigned long long* xp =
        reinterpret_cast<const unsigned long long*>(g_xpT) + t;  // pair t, stride 512/h

    #pragma unroll 2
    for (int h = 0; h < HID; h++) {
        const unsigned long long xx = xp[h * (N_S / 2)];          // LDG.64
        const unsigned long long ww = s_w[h];                     // LDS.64 bcast
        const ulonglong2 ya = *reinterpret_cast<const ulonglong2*>(&s_y[h][0]);
        const ulonglong2 yb = *reinterpret_cast<const ulonglong2*>(&s_y[h][2]);
        const ulonglong2 yc = *reinterpret_cast<const ulonglong2*>(&s_y[h][4]);
        const ulonglong2 yd = *reinterpret_cast<const ulonglong2*>(&s_y[h][6]);
        const unsigned long long yv[8] = {ya.x, ya.y, yb.x, yb.y,
                                          yc.x, yc.y, yd.x, yd.y};
        #pragma unroll
        for (int i = 0; i < 8; i++) {
            acc[i] = f2fma(f2relu(f2add(yv[i], xx)), ww, acc[i]);
        }
    }

    // Epilogue: per-i exp-sum over 1024 j (this thread holds j = 2t, 2t+1)
    const float b2v = b2[0];
    const int lane = t & 31, wid = t >> 5;

    #pragma unroll
    for (int i = 0; i < 8; i++) {
        const int ig = ib + i;
        unsigned lo, hi;
        asm("mov.b64 {%0,%1},%2;" : "=r"(lo), "=r"(hi) : "l"(acc[i]));
        const float v0 = __uint_as_float(lo) + b2v;
        const float v1 = __uint_as_float(hi) + b2v;
        if (2 * t     == ig) g_t0[ig] = v0;   // diagonal: T0[i] = T1[i,i]
        if (2 * t + 1 == ig) g_t0[ig] = v1;

        float s = __expf(v0) + __expf(v1);
        #pragma unroll
        for (int o = 16; o > 0; o >>= 1) s += __shfl_xor_sync(0xffffffffu, s, o);
        if (lane == 0) red[wid] = s;
        __syncthreads();
        if (t < 16) {
            float r = red[t];
            #pragma unroll
            for (int o = 8; o > 0; o >>= 1) r += __shfl_xor_sync(0x0000ffffu, r, o);
            if (t == 0) g_lse[ig] = logf(r);
        }
        __syncthreads();
    }
}

// ---------------------------------------------------------------------------
// Finalize: lb = mean(T0) - (mean(lse) - log(N))
// ---------------------------------------------------------------------------
__global__ void __launch_bounds__(256) finalize_kernel(float* __restrict__ out) {
    __shared__ float r1[256], r2[256];
    const int t = threadIdx.x;
    float a = 0.f, b = 0.f;
    #pragma unroll
    for (int p = 0; p < 4; p++) {
        a += g_t0[t + 256 * p];
        b += g_lse[t + 256 * p];
    }
    r1[t] = a; r2[t] = b;
    __syncthreads();
    for (int off = 128; off > 0; off >>= 1) {
        if (t < off) { r1[t] += r1[t + off]; r2[t] += r2[t + off]; }
        __syncthreads();
    }
    if (t == 0) {
        out[0] = r1[0] / (float)N_S - (r2[0] / (float)N_S - logf((float)N_S));
    }
}

// ---------------------------------------------------------------------------
extern "C" void kernel_launch(void* const* d_in, const int* in_sizes, int n_in,
                              void* d_out, int out_size) {
    const float* x  = (const float*)d_in[0];
    const float* y  = (const float*)d_in[1];
    const float* W1 = (const float*)d_in[2];
    const float* b1 = (const float*)d_in[3];
    const float* W2 = (const float*)d_in[4];
    const float* b2 = (const float*)d_in[5];

    proj_kernel<<<dim3(128, 2), 256>>>(x, y, W1, b1);
    main_kernel<<<128, 512>>>(W2, b2);
    finalize_kernel<<<1, 256>>>((float*)d_out);
}

// round 3
// speedup vs baseline: 2.0749x; 1.5762x over previous
#include <cuda_runtime.h>
#include <math.h>

#define N_S 1024
#define XD  128
#define HID 256

typedef unsigned long long u64;

__device__ __align__(16) float g_xpT[HID * N_S];   // xp transposed: [h][j]
__device__ __align__(16) float g_ypb[N_S * HID];   // yp + b1:       [i][h]
__device__ float g_t0[N_S];
__device__ float g_lse[N_S];

// ---------------------------------------------------------------------------
// packed f32x2 helpers (sm_103a)
// ---------------------------------------------------------------------------
__device__ __forceinline__ u64 f2add(u64 a, u64 b) {
    u64 r; asm("add.rn.f32x2 %0,%1,%2;" : "=l"(r) : "l"(a), "l"(b)); return r;
}
__device__ __forceinline__ u64 f2fma(u64 a, u64 b, u64 c) {
    u64 r; asm("fma.rn.f32x2 %0,%1,%2,%3;" : "=l"(r) : "l"(a), "l"(b), "l"(c));
    return r;
}
__device__ __forceinline__ u64 f2relu(u64 a) {
    unsigned lo, hi;
    asm("mov.b64 {%0,%1},%2;" : "=r"(lo), "=r"(hi) : "l"(a));
    float flo = fmaxf(__uint_as_float(lo), 0.f);
    float fhi = fmaxf(__uint_as_float(hi), 0.f);
    u64 r;
    asm("mov.b64 %0,{%1,%2};" : "=l"(r)
        : "r"(__float_as_uint(flo)), "r"(__float_as_uint(fhi)));
    return r;
}
__device__ __forceinline__ u64 dupf(float v) {
    unsigned u = __float_as_uint(v);
    u64 r; asm("mov.b64 %0,{%1,%1};" : "=l"(r) : "r"(u)); return r;
}

// ---------------------------------------------------------------------------
// Projection: xp = x @ W1[:128] (transposed store), ypb = y @ W1[128:] + b1
// grid (256, 2), block 256, 4 rows/CTA. Explicit 8-deep W prefetch ring.
// ---------------------------------------------------------------------------
__global__ void __launch_bounds__(256) proj_kernel(const float* __restrict__ x,
                                                   const float* __restrict__ y,
                                                   const float* __restrict__ W1,
                                                   const float* __restrict__ b1) {
    __shared__ __align__(16) float xs[4][XD];
    const int t  = threadIdx.x;          // hidden index h
    const int rb = blockIdx.x * 4;       // row base
    const float* src = (blockIdx.y == 0) ? x : y;

    for (int idx = t; idx < 4 * XD; idx += 256) {
        xs[idx >> 7][idx & 127] = src[(rb + (idx >> 7)) * XD + (idx & 127)];
    }
    __syncthreads();

    const float* Wb = W1 + (blockIdx.y == 0 ? 0 : XD * HID);

    float acc0 = 0.f, acc1 = 0.f, acc2 = 0.f, acc3 = 0.f;
    float wb[8];
    #pragma unroll
    for (int p = 0; p < 8; p++) wb[p] = Wb[p * HID + t];   // prefetch ring

    for (int kb = 0; kb < XD; kb += 8) {
        // stage x for this chunk as vectors
        float4 xa0 = *reinterpret_cast<const float4*>(&xs[0][kb]);
        float4 xb0 = *reinterpret_cast<const float4*>(&xs[0][kb + 4]);
        float4 xa1 = *reinterpret_cast<const float4*>(&xs[1][kb]);
        float4 xb1 = *reinterpret_cast<const float4*>(&xs[1][kb + 4]);
        float4 xa2 = *reinterpret_cast<const float4*>(&xs[2][kb]);
        float4 xb2 = *reinterpret_cast<const float4*>(&xs[2][kb + 4]);
        float4 xa3 = *reinterpret_cast<const float4*>(&xs[3][kb]);
        float4 xb3 = *reinterpret_cast<const float4*>(&xs[3][kb + 4]);
        float xv0[8] = {xa0.x, xa0.y, xa0.z, xa0.w, xb0.x, xb0.y, xb0.z, xb0.w};
        float xv1[8] = {xa1.x, xa1.y, xa1.z, xa1.w, xb1.x, xb1.y, xb1.z, xb1.w};
        float xv2[8] = {xa2.x, xa2.y, xa2.z, xa2.w, xb2.x, xb2.y, xb2.z, xb2.w};
        float xv3[8] = {xa3.x, xa3.y, xa3.z, xa3.w, xb3.x, xb3.y, xb3.z, xb3.w};

        #pragma unroll
        for (int p = 0; p < 8; p++) {
            const float w = wb[p];
            if (kb < XD - 8) wb[p] = Wb[(kb + 8 + p) * HID + t];  // refill ring
            acc0 = fmaf(xv0[p], w, acc0);
            acc1 = fmaf(xv1[p], w, acc1);
            acc2 = fmaf(xv2[p], w, acc2);
            acc3 = fmaf(xv3[p], w, acc3);
        }
    }

    if (blockIdx.y == 0) {
        // transposed store: one STG.128 per thread
        float4 v = make_float4(acc0, acc1, acc2, acc3);
        *reinterpret_cast<float4*>(&g_xpT[t * N_S + rb]) = v;
    } else {
        const float bb = b1[t];
        g_ypb[(rb + 0) * HID + t] = acc0 + bb;
        g_ypb[(rb + 1) * HID + t] = acc1 + bb;
        g_ypb[(rb + 2) * HID + t] = acc2 + bb;
        g_ypb[(rb + 3) * HID + t] = acc3 + bb;
    }
}

// ---------------------------------------------------------------------------
// Main: T1[i,j] = sum_h relu(ypb[i,h] + xp[j,h]) * W2[h]  (+b2 in epilogue)
// grid 148 (136 CTAs x 7 i-rows + 12 x 6), block 512, full j per CTA.
// Thread t owns j-pair (2t,2t+1) as packed f32x2; 8-deep xp prefetch ring.
// ---------------------------------------------------------------------------
__global__ void __launch_bounds__(512) main_kernel(const float* __restrict__ W2,
                                                   const float* __restrict__ b2) {
    __shared__ __align__(16) u64 s_y[HID][8];   // [h][i] dup pairs (7 used)
    __shared__ __align__(16) u64 s_w[HID];      // dup pairs
    __shared__ float red[128];                  // [i][warp] partials

    const int t   = threadIdx.x;
    const int cta = blockIdx.x;
    const int nrows = (cta < 136) ? 7 : 6;
    const int ib    = (cta < 136) ? cta * 7 : 952 + (cta - 136) * 6;

    // stage ypb dup pairs (7 rows; clamp for 6-row CTAs) and W2
    for (int idx = t; idx < HID * 7; idx += 512) {
        const int h = idx & 255;
        int p = idx >> 8;                        // 0..6
        const int pr = (p < nrows) ? p : nrows - 1;
        s_y[h][p] = dupf(g_ypb[(ib + pr) * HID + h]);
    }
    if (t < HID) s_w[t] = dupf(W2[t]);
    __syncthreads();

    u64 acc[7];
    #pragma unroll
    for (int i = 0; i < 7; i++) acc[i] = 0ull;

    const u64* xp = reinterpret_cast<const u64*>(g_xpT) + t;  // pair t, +512/h

    u64 xb[8];
    #pragma unroll
    for (int p = 0; p < 8; p++) xb[p] = xp[p * (N_S / 2)];    // prefetch ring

    for (int hb = 0; hb < HID; hb += 8) {
        #pragma unroll
        for (int p = 0; p < 8; p++) {
            const int h = hb + p;
            const u64 xx = xb[p];
            if (hb < HID - 8) xb[p] = xp[(h + 8) * (N_S / 2)];  // refill
            const u64 ww = s_w[h];
            const ulonglong2 ya = *reinterpret_cast<const ulonglong2*>(&s_y[h][0]);
            const ulonglong2 yc = *reinterpret_cast<const ulonglong2*>(&s_y[h][2]);
            const ulonglong2 ye = *reinterpret_cast<const ulonglong2*>(&s_y[h][4]);
            const u64 yg = s_y[h][6];
            acc[0] = f2fma(f2relu(f2add(ya.x, xx)), ww, acc[0]);
            acc[1] = f2fma(f2relu(f2add(ya.y, xx)), ww, acc[1]);
            acc[2] = f2fma(f2relu(f2add(yc.x, xx)), ww, acc[2]);
            acc[3] = f2fma(f2relu(f2add(yc.y, xx)), ww, acc[3]);
            acc[4] = f2fma(f2relu(f2add(ye.x, xx)), ww, acc[4]);
            acc[5] = f2fma(f2relu(f2add(ye.y, xx)), ww, acc[5]);
            acc[6] = f2fma(f2relu(f2add(yg,   xx)), ww, acc[6]);
        }
    }

    // Epilogue: per-i exp-sums; one barrier total.
    const float b2v = b2[0];
    const int lane = t & 31, wid = t >> 5;

    #pragma unroll
    for (int i = 0; i < 7; i++) {
        const int ig = ib + i;
        unsigned lo, hi;
        asm("mov.b64 {%0,%1},%2;" : "=r"(lo), "=r"(hi) : "l"(acc[i]));
        const float v0 = __uint_as_float(lo) + b2v;
        const float v1 = __uint_as_float(hi) + b2v;
        if (i < nrows) {
            if (2 * t     == ig) g_t0[ig] = v0;   // diagonal T0
            if (2 * t + 1 == ig) g_t0[ig] = v1;
        }
        float s = __expf(v0) + __expf(v1);
        #pragma unroll
        for (int o = 16; o > 0; o >>= 1) s += __shfl_xor_sync(0xffffffffu, s, o);
        if (lane == 0) red[i * 16 + wid] = s;
    }
    if (t < 16) red[112 + t] = 1.0f;             // pad row i=7
    __syncthreads();

    if (t < 128) {
        const int i = t >> 4;                    // 0..7
        float r = red[t];
        #pragma unroll
        for (int o = 8; o > 0; o >>= 1) r += __shfl_xor_sync(0xffffffffu, r, o);
        if ((t & 15) == 0 && i < nrows) g_lse[ib + i] = logf(r);
    }
}

// ---------------------------------------------------------------------------
// Finalize: lb = mean(T0) - (mean(lse) - log(N))
// ---------------------------------------------------------------------------
__global__ void __launch_bounds__(256) finalize_kernel(float* __restrict__ out) {
    __shared__ float r1[256], r2[256];
    const int t = threadIdx.x;
    float a = 0.f, b = 0.f;
    #pragma unroll
    for (int p = 0; p < 4; p++) {
        a += g_t0[t + 256 * p];
        b += g_lse[t + 256 * p];
    }
    r1[t] = a; r2[t] = b;
    __syncthreads();
    for (int off = 128; off > 0; off >>= 1) {
        if (t < off) { r1[t] += r1[t + off]; r2[t] += r2[t + off]; }
        __syncthreads();
    }
    if (t == 0) {
        out[0] = r1[0] / (float)N_S - (r2[0] / (float)N_S - logf((float)N_S));
    }
}

// ---------------------------------------------------------------------------
extern "C" void kernel_launch(void* const* d_in, const int* in_sizes, int n_in,
                              void* d_out, int out_size) {
    const float* x  = (const float*)d_in[0];
    const float* y  = (const float*)d_in[1];
    const float* W1 = (const float*)d_in[2];
    const float* b1 = (const float*)d_in[3];
    const float* W2 = (const float*)d_in[4];
    const float* b2 = (const float*)d_in[5];

    proj_kernel<<<dim3(256, 2), 256>>>(x, y, W1, b1);
    main_kernel<<<148, 512>>>(W2, b2);
    finalize_kernel<<<1, 256>>>((float*)d_out);
}